// round 9
// baseline (speedup 1.0000x reference)
#include <cuda_runtime.h>

#define S_   500
#define XY_  10
#define ZD_  5
#define NT_  10000
#define B_   32
#define T_   40
#define L_   20

// Scratch (allocation-free rule: __device__ globals)
__device__ float g_em[B_ * T_ * S_];   // per-(b,t) emission sums (~2.56 MB)

// ---------------------------------------------------------------------------
// Kernel 1: em[bt,s] = sum_l LE[s, tok[bt,l]]
// One block per state s. Load row LE[s,:] (40 KB) into SMEM coalesced, then
// gather tokens from SMEM (random banks, but on-chip). DRAM: table read once.
// 512 threads -> 4 CTAs/SM (smem 40KB x4 = 160KB < 228KB), single wave.
// ---------------------------------------------------------------------------
__global__ __launch_bounds__(512)
void k_em2(const float* __restrict__ LE, const int* __restrict__ stories) {
    __shared__ float row[NT_];            // 40 KB
    const int s = blockIdx.x;
    const int tid = threadIdx.x;

    // coalesced row load, vectorized
    {
        const float4* src = (const float4*)(LE + s * NT_);
        float4* dst = (float4*)row;
        #pragma unroll
        for (int i = tid; i < NT_ / 4; i += 512) dst[i] = src[i];
    }
    __syncthreads();

    #pragma unroll
    for (int bt = tid; bt < B_ * T_; bt += 512) {
        const int* tk = stories + bt * L_;
        float acc = 0.f;
        #pragma unroll
        for (int l = 0; l < L_; l++) acc += row[tk[l]];
        g_em[bt * S_ + s] = acc;          // 4B scattered; merges in L2 (em resident)
    }
}

// ---------------------------------------------------------------------------
// Orderable-int key for float max via redux.sync.max.u32
// ---------------------------------------------------------------------------
__device__ __forceinline__ unsigned fkey(float f) {
    int i = __float_as_int(f);
    return (unsigned)(i ^ ((i >> 31) | 0x80000000));
}
__device__ __forceinline__ float keyf(unsigned k) {
    int i = (int)k;
    i = i ^ (((~i) >> 31) | 0x80000000);
    return __int_as_float(i);
}
__device__ __forceinline__ unsigned redux_max(unsigned k) {
    unsigned r;
    asm volatile("redux.sync.max.u32 %0, %1, 0xffffffff;" : "=r"(r) : "r"(k));
    return r;
}

// ---------------------------------------------------------------------------
// Kernel 2: forward recursion. One CTA per batch.
// Carry p_j = exp(alpha_j - M) in SMEM (M = block max of alpha), so each step
// needs only 1 EX2 + 1 LG2 per state (edge probs P_d = exp(logT) precomputed
// in registers). Exact per-row fallback if the shifted sum underflows.
// ---------------------------------------------------------------------------
__global__ __launch_bounds__(512, 1)
void k_forward(const float* __restrict__ priors,
               const float* __restrict__ logT,
               float* __restrict__ out) {
    __shared__ float pA[512], pB[512];    // p = exp(alpha - M)
    __shared__ float aA[512], aB[512];    // alpha (fallback only)
    __shared__ unsigned wmax[16];

    const int b = blockIdx.x;
    const int s = threadIdx.x;
    const int sc = (s < S_) ? s : (S_ - 1);   // threads >=500 duplicate state 499
    const int wid = s >> 5;
    const int lane = s & 31;

    int   jn[7];
    float tv[7];   // log transition (fallback)
    float pw[7];   // exp(log transition) = prob

    {
        const int z = sc / 100, r = sc % 100, y = r / 10, x = r % 10;
        const int dx[7] = {0, 1,-1, 0, 0, 0, 0};
        const int dy[7] = {0, 0, 0, 1,-1, 0, 0};
        const int dz[7] = {0, 0, 0, 0, 0, 1, 2};
        #pragma unroll
        for (int d = 0; d < 7; d++) {
            int nx = x + dx[d], ny = y + dy[d], nz = z + dz[d];
            bool v = ((unsigned)nx < XY_) & ((unsigned)ny < XY_) & ((unsigned)nz < ZD_);
            int jj = v ? (nx + XY_ * (ny + XY_ * nz)) : sc;
            jn[d] = jj;
            tv[d] = v ? logT[sc * S_ + jj] : -1e9f;
            pw[d] = v ? __expf(tv[d]) : 0.f;
        }
    }

    float* pc = pA; float* pn = pB;
    float* ac = aA; float* an = aB;

    // ---- t = 0 ----
    float anew = g_em[(b * T_ + 0) * S_ + sc] + priors[sc];
    if (s < S_) out[0 * B_ * S_ + b * S_ + s] = anew;
    {
        unsigned wm = redux_max(fkey(anew));
        if (lane == 0) wmax[wid] = wm;
        ac[s] = anew;
    }
    __syncthreads();
    float M;
    {
        unsigned mk = wmax[0];
        #pragma unroll
        for (int i = 1; i < 16; i++) mk = max(mk, wmax[i]);
        M = keyf(mk);
        pc[s] = __expf(anew - M);
    }
    __syncthreads();

    float em_next = g_em[(b * T_ + 1) * S_ + sc];

    for (int t = 1; t < T_; t++) {
        const float emv = em_next;
        if (t + 1 < T_) em_next = g_em[(b * T_ + t + 1) * S_ + sc];

        // shared-shift path: sum_d P_d * p[j_d]
        float f0 = pw[0] * pc[jn[0]];
        float f1 = pw[1] * pc[jn[1]];
        float f2 = pw[2] * pc[jn[2]];
        float f3 = pw[3] * pc[jn[3]];
        float f4 = pw[4] * pc[jn[4]];
        float f5 = pw[5] * pc[jn[5]];
        float f6 = pw[6] * pc[jn[6]];
        float sum = ((f0 + f1) + (f2 + f3)) + ((f4 + f5) + f6);

        if (sum >= 1e-37f) {
            anew = emv + M + __logf(sum);
        } else {
            // exact per-row fallback (rare): recompute from alpha
            float v0 = tv[0] + ac[jn[0]];
            float v1 = tv[1] + ac[jn[1]];
            float v2 = tv[2] + ac[jn[2]];
            float v3 = tv[3] + ac[jn[3]];
            float v4 = tv[4] + ac[jn[4]];
            float v5 = tv[5] + ac[jn[5]];
            float v6 = tv[6] + ac[jn[6]];
            float m = fmaxf(fmaxf(fmaxf(v0, v1), fmaxf(v2, v3)),
                            fmaxf(fmaxf(v4, v5), v6));
            float s2 = __expf(v0 - m) + __expf(v1 - m) + __expf(v2 - m)
                     + __expf(v3 - m) + __expf(v4 - m) + __expf(v5 - m)
                     + __expf(v6 - m);
            anew = emv + m + __logf(s2);
        }

        if (s < S_) out[t * B_ * S_ + b * S_ + s] = anew;

        unsigned wm = redux_max(fkey(anew));
        if (lane == 0) wmax[wid] = wm;
        an[s] = anew;
        __syncthreads();

        unsigned mk = wmax[0];
        #pragma unroll
        for (int i = 1; i < 16; i++) mk = max(mk, wmax[i]);
        float Mn = keyf(mk);
        pn[s] = __expf(anew - Mn);
        __syncthreads();

        { float* tp = pc; pc = pn; pn = tp; }
        { float* ta = ac; ac = an; an = ta; }
        M = Mn;
    }
}

// ---------------------------------------------------------------------------
extern "C" void kernel_launch(void* const* d_in, const int* in_sizes, int n_in,
                              void* d_out, int out_size) {
    const float* log_priors      = (const float*)d_in[0];
    const float* log_transitions = (const float*)d_in[1];
    const float* log_emissions   = (const float*)d_in[2];
    const int*   stories         = (const int*)d_in[3];
    float* out = (float*)d_out;

    k_em2<<<S_, 512>>>(log_emissions, stories);
    k_forward<<<B_, 512>>>(log_priors, log_transitions, out);
}

// round 10
// speedup vs baseline: 1.2844x; 1.2844x over previous
#include <cuda_runtime.h>

#define S_   500
#define XY_  10
#define ZD_  5
#define NT_  10000
#define B_   32
#define T_   40
#define L_   20
#define BT_  (B_ * T_)   // 1280

// Scratch (allocation-free rule: __device__ globals)
__device__ float g_emT[S_ * BT_];   // em transposed: [s, bt]  (~2.56 MB)

// ---------------------------------------------------------------------------
// Kernel 1: emT[s, bt] = sum_l LE[s, tok[bt,l]]
// One block per state s. Row LE[s,:] (40 KB) -> SMEM coalesced; token gathers
// hit SMEM; writes are coalesced over bt (lanes = consecutive bt).
// ---------------------------------------------------------------------------
__global__ __launch_bounds__(512)
void k_em2(const float* __restrict__ LE, const int* __restrict__ stories) {
    __shared__ float row[NT_];            // 40 KB
    const int s = blockIdx.x;
    const int tid = threadIdx.x;

    {
        const float4* src = (const float4*)(LE + s * NT_);
        float4* dst = (float4*)row;
        #pragma unroll
        for (int i = tid; i < NT_ / 4; i += 512) dst[i] = src[i];
    }
    __syncthreads();

    #pragma unroll
    for (int bt = tid; bt < BT_; bt += 512) {
        const int4* tk4 = (const int4*)(stories + bt * L_);   // 80B, 16B-aligned
        float acc = 0.f;
        #pragma unroll
        for (int q = 0; q < L_ / 4; q++) {
            int4 t4 = tk4[q];
            acc += row[t4.x] + row[t4.y] + row[t4.z] + row[t4.w];
        }
        g_emT[s * BT_ + bt] = acc;        // coalesced
    }
}

// ---------------------------------------------------------------------------
// Orderable-int key for float max via redux.sync.max.u32
// ---------------------------------------------------------------------------
__device__ __forceinline__ unsigned fkey(float f) {
    int i = __float_as_int(f);
    return (unsigned)(i ^ ((i >> 31) | 0x80000000));
}
__device__ __forceinline__ float keyf(unsigned k) {
    int i = (int)k;
    i = i ^ (((~i) >> 31) | 0x80000000);
    return __int_as_float(i);
}
__device__ __forceinline__ unsigned redux_max(unsigned k) {
    unsigned r;
    asm volatile("redux.sync.max.u32 %0, %1, 0xffffffff;" : "=r"(r) : "r"(k));
    return r;
}

// ---------------------------------------------------------------------------
// Kernel 2: forward recursion. One CTA per batch. ONE barrier per step.
//
// Invariant: pbuf[par][j] = exp(alpha_j - shift_prev), shift_prev uniform and
// register-carried by every thread. anew = em + shift_prev + log(sum) is
// EXACT for any shift; the shift is kept centered by combining last step's
// exact block max (redux -> wmax, read back with 1 LDS + 1 redux, no chain)
// with a per-step drift Darr[t] (reference-state em). Any over/underflow of
// the provisional shift makes sum inf/0/NaN -> exact per-row fallback.
// ---------------------------------------------------------------------------
__global__ __launch_bounds__(512, 1)
void k_forward(const float* __restrict__ priors,
               const float* __restrict__ logT,
               float* __restrict__ out) {
    __shared__ float pbuf[2][512];        // exp(alpha - shift)
    __shared__ float abuf[2][512];        // alpha (fallback + init)
    __shared__ unsigned wmax[2][16];      // per-warp max keys, double-buffered
    __shared__ float Darr[T_];            // reference-state em per t

    const int b = blockIdx.x;
    const int s = threadIdx.x;
    const int sc = (s < S_) ? s : (S_ - 1);
    const int wid = s >> 5;
    const int lane = s & 31;

    int   jn[7];
    float tv[7];   // log transition (fallback)
    float pw[7];   // exp(log transition)

    {
        const int z = sc / 100, r = sc % 100, y = r / 10, x = r % 10;
        const int dx[7] = {0, 1,-1, 0, 0, 0, 0};
        const int dy[7] = {0, 0, 0, 1,-1, 0, 0};
        const int dz[7] = {0, 0, 0, 0, 0, 1, 2};
        #pragma unroll
        for (int d = 0; d < 7; d++) {
            int nx = x + dx[d], ny = y + dy[d], nz = z + dz[d];
            bool v = ((unsigned)nx < XY_) & ((unsigned)ny < XY_) & ((unsigned)nz < ZD_);
            int jj = v ? (nx + XY_ * (ny + XY_ * nz)) : sc;
            jn[d] = jj;
            tv[d] = v ? logT[sc * S_ + jj] : -1e9f;
            pw[d] = v ? __expf(tv[d]) : 0.f;
        }
    }

    // reference-state (s=0) em drift values
    if (s < T_) Darr[s] = g_emT[0 * BT_ + b * T_ + s];

    // ---- t = 0 ----
    float a0 = g_emT[sc * BT_ + b * T_ + 0] + priors[sc];
    if (s < S_) out[0 * B_ * S_ + b * S_ + s] = a0;
    {
        unsigned wm = redux_max(fkey(a0));
        if (lane == 0) wmax[0][wid] = wm;
        abuf[0][s] = a0;
    }
    __syncthreads();

    float shift_prev;
    {
        unsigned mk = redux_max(wmax[0][lane & 15]);   // broadcast-LDS + redux
        shift_prev = keyf(mk);                          // exact max of alpha0
        pbuf[0][s] = __expf(a0 - shift_prev);
    }
    float em_next = g_emT[sc * BT_ + b * T_ + 1];
    __syncthreads();

    for (int t = 1; t < T_; t++) {
        const int pr = (t - 1) & 1, cu = t & 1;
        const float emv = em_next;
        if (t + 1 < T_) em_next = g_emT[sc * BT_ + b * T_ + t + 1];

        // exact max of previous alphas (off critical path of anew)
        const float Mprev = keyf(redux_max(wmax[pr][lane & 15]));
        const float shift_cur = Mprev + Darr[t];        // uniform provisional shift

        const float* pc = pbuf[pr];
        float f0 = pw[0] * pc[jn[0]];
        float f1 = pw[1] * pc[jn[1]];
        float f2 = pw[2] * pc[jn[2]];
        float f3 = pw[3] * pc[jn[3]];
        float f4 = pw[4] * pc[jn[4]];
        float f5 = pw[5] * pc[jn[5]];
        float f6 = pw[6] * pc[jn[6]];
        float sum = ((f0 + f1) + (f2 + f3)) + ((f4 + f5) + f6);

        float anew;
        if (sum > 1e-30f && sum < 1e30f) {
            anew = emv + shift_prev + __logf(sum);
        } else {
            // exact per-row fallback (rare; also catches inf/NaN sums)
            const float* ac = abuf[pr];
            float v0 = tv[0] + ac[jn[0]];
            float v1 = tv[1] + ac[jn[1]];
            float v2 = tv[2] + ac[jn[2]];
            float v3 = tv[3] + ac[jn[3]];
            float v4 = tv[4] + ac[jn[4]];
            float v5 = tv[5] + ac[jn[5]];
            float v6 = tv[6] + ac[jn[6]];
            float m = fmaxf(fmaxf(fmaxf(v0, v1), fmaxf(v2, v3)),
                            fmaxf(fmaxf(v4, v5), v6));
            float s2 = __expf(v0 - m) + __expf(v1 - m) + __expf(v2 - m)
                     + __expf(v3 - m) + __expf(v4 - m) + __expf(v5 - m)
                     + __expf(v6 - m);
            anew = emv + m + __logf(s2);
        }

        if (s < S_) out[t * B_ * S_ + b * S_ + s] = anew;

        unsigned wm = redux_max(fkey(anew));
        if (lane == 0) wmax[cu][wid] = wm;
        abuf[cu][s] = anew;
        pbuf[cu][s] = __expf(anew - shift_cur);
        shift_prev = shift_cur;
        __syncthreads();                                // the only barrier
    }
}

// ---------------------------------------------------------------------------
extern "C" void kernel_launch(void* const* d_in, const int* in_sizes, int n_in,
                              void* d_out, int out_size) {
    const float* log_priors      = (const float*)d_in[0];
    const float* log_transitions = (const float*)d_in[1];
    const float* log_emissions   = (const float*)d_in[2];
    const int*   stories         = (const int*)d_in[3];
    float* out = (float*)d_out;

    k_em2<<<S_, 512>>>(log_emissions, stories);
    k_forward<<<B_, 512>>>(log_priors, log_transitions, out);
}